// round 1
// baseline (speedup 1.0000x reference)
#include <cuda_runtime.h>
#include <math.h>

#define N_NODES 500000
#define N_EDGES 8000000
#define IN_DIM  128
#define H1      32
#define H2      16

// ---------------- constant-memory weights (uniform LDCU operands for FFMA) --
__constant__ float cW1[IN_DIM * H1];   // 16 KB
__constant__ float cb1[H1];
__constant__ float cW2[H1 * H2];
__constant__ float cb2[H2];
__constant__ float cWfc[H2 * 2];
__constant__ float cbfc[2];

// ---------------- scratch (static device globals; no runtime allocation) ----
__device__ unsigned g_deg[N_NODES];
__device__ float    g_dinv[N_NODES];
__device__ float    g_y1[(size_t)N_NODES * H1];  // (x@W1)*dinv
__device__ float    g_z1[(size_t)N_NODES * H1];  // accumulator (init = y1)
__device__ float    g_y2[(size_t)N_NODES * H2];
__device__ float    g_z2[(size_t)N_NODES * H2];
__device__ int      g_is64;                      // edge_index dtype flag

// ---------------- edge index access (dtype-agnostic) ------------------------
__device__ __forceinline__ int edge_at(const void* ei, long long idx) {
    if (g_is64) return (int)((const long long*)ei)[idx];
    return ((const int*)ei)[idx];
}

// Detect int64 vs int32 edge_index: int64 values < 500000 have zero high words.
__global__ void k_detect(const unsigned* __restrict__ ei32) {
    if (blockIdx.x == 0 && threadIdx.x == 0) {
        int is64 = 1;
        for (int e = 0; e < 1024; e++) {
            if (ei32[2 * e + 1] != 0u) { is64 = 0; break; }
        }
        g_is64 = is64;
    }
}

// ---------------- degree / norm ---------------------------------------------
__global__ void k_deg_init() {
    int i = blockIdx.x * blockDim.x + threadIdx.x;
    if (i < N_NODES) g_deg[i] = 1u;  // self-loop
}

__global__ void k_deg_count(const void* __restrict__ ei) {
    int e = blockIdx.x * blockDim.x + threadIdx.x;
    if (e < N_EDGES) {
        int d = edge_at(ei, (long long)N_EDGES + e);  // dst half
        atomicAdd(&g_deg[d], 1u);
    }
}

__global__ void k_dinv() {
    int i = blockIdx.x * blockDim.x + threadIdx.x;
    if (i < N_NODES) g_dinv[i] = rsqrtf((float)g_deg[i]);
}

// ---------------- layer 1 GEMM: y1 = (x @ W1) * dinv ; z1 = y1 --------------
__global__ void k_gemm1(const float* __restrict__ x) {
    int i = blockIdx.x * blockDim.x + threadIdx.x;
    if (i >= N_NODES) return;

    float acc[H1];
#pragma unroll
    for (int o = 0; o < H1; o++) acc[o] = 0.0f;

    const float4* xr = (const float4*)(x + (size_t)i * IN_DIM);
#pragma unroll 2
    for (int kk = 0; kk < IN_DIM / 4; kk++) {
        float4 v = __ldg(xr + kk);
        int k = kk * 4;
#pragma unroll
        for (int o = 0; o < H1; o++) {
            float a = acc[o];
            a = fmaf(v.x, cW1[(k + 0) * H1 + o], a);
            a = fmaf(v.y, cW1[(k + 1) * H1 + o], a);
            a = fmaf(v.z, cW1[(k + 2) * H1 + o], a);
            a = fmaf(v.w, cW1[(k + 3) * H1 + o], a);
            acc[o] = a;
        }
    }

    float di = g_dinv[i];
    float4* y = (float4*)(g_y1 + (size_t)i * H1);
    float4* z = (float4*)(g_z1 + (size_t)i * H1);
#pragma unroll
    for (int q = 0; q < H1 / 4; q++) {
        float4 t;
        t.x = acc[q * 4 + 0] * di;
        t.y = acc[q * 4 + 1] * di;
        t.z = acc[q * 4 + 2] * di;
        t.w = acc[q * 4 + 3] * di;
        y[q] = t;
        z[q] = t;  // self-loop contribution pre-seeded
    }
}

// ---------------- edge scatter L1: z1[dst] += y1[src] (32 floats/edge) ------
__global__ void k_scatter1(const void* __restrict__ ei) {
    long long t = (long long)blockIdx.x * blockDim.x + threadIdx.x;
    int e = (int)(t >> 3);
    int q = (int)(t & 7);
    if (e >= N_EDGES) return;
    int s = edge_at(ei, e);
    int d = edge_at(ei, (long long)N_EDGES + e);
    float4 v = __ldg((const float4*)(g_y1 + (size_t)s * H1) + q);
    atomicAdd((float4*)(g_z1 + (size_t)d * H1) + q, v);
}

// ---------------- layer 2: h1=relu(dinv*z1+b1); y2=(h1@W2)*dinv; z2=y2 ------
__global__ void k_layer2() {
    int i = blockIdx.x * blockDim.x + threadIdx.x;
    if (i >= N_NODES) return;
    float di = g_dinv[i];

    float h[H1];
    const float4* z = (const float4*)(g_z1 + (size_t)i * H1);
#pragma unroll
    for (int q = 0; q < H1 / 4; q++) {
        float4 v = z[q];
        h[q * 4 + 0] = fmaxf(fmaf(di, v.x, cb1[q * 4 + 0]), 0.0f);
        h[q * 4 + 1] = fmaxf(fmaf(di, v.y, cb1[q * 4 + 1]), 0.0f);
        h[q * 4 + 2] = fmaxf(fmaf(di, v.z, cb1[q * 4 + 2]), 0.0f);
        h[q * 4 + 3] = fmaxf(fmaf(di, v.w, cb1[q * 4 + 3]), 0.0f);
    }

    float acc[H2];
#pragma unroll
    for (int o = 0; o < H2; o++) acc[o] = 0.0f;
#pragma unroll 4
    for (int k = 0; k < H1; k++) {
        float hv = h[k];
#pragma unroll
        for (int o = 0; o < H2; o++)
            acc[o] = fmaf(hv, cW2[k * H2 + o], acc[o]);
    }

    float4* y = (float4*)(g_y2 + (size_t)i * H2);
    float4* zz = (float4*)(g_z2 + (size_t)i * H2);
#pragma unroll
    for (int q = 0; q < H2 / 4; q++) {
        float4 t;
        t.x = acc[q * 4 + 0] * di;
        t.y = acc[q * 4 + 1] * di;
        t.z = acc[q * 4 + 2] * di;
        t.w = acc[q * 4 + 3] * di;
        y[q] = t;
        zz[q] = t;
    }
}

// ---------------- edge scatter L2: z2[dst] += y2[src] (16 floats/edge) ------
__global__ void k_scatter2(const void* __restrict__ ei) {
    long long t = (long long)blockIdx.x * blockDim.x + threadIdx.x;
    int e = (int)(t >> 2);
    int q = (int)(t & 3);
    if (e >= N_EDGES) return;
    int s = edge_at(ei, e);
    int d = edge_at(ei, (long long)N_EDGES + e);
    float4 v = __ldg((const float4*)(g_y2 + (size_t)s * H2) + q);
    atomicAdd((float4*)(g_z2 + (size_t)d * H2) + q, v);
}

// ---------------- final: h2=relu(dinv*z2+b2); logits; log_softmax -----------
__global__ void k_final(float* __restrict__ out) {
    int i = blockIdx.x * blockDim.x + threadIdx.x;
    if (i >= N_NODES) return;
    float di = g_dinv[i];

    float h[H2];
    const float4* z = (const float4*)(g_z2 + (size_t)i * H2);
#pragma unroll
    for (int q = 0; q < H2 / 4; q++) {
        float4 v = z[q];
        h[q * 4 + 0] = fmaxf(fmaf(di, v.x, cb2[q * 4 + 0]), 0.0f);
        h[q * 4 + 1] = fmaxf(fmaf(di, v.y, cb2[q * 4 + 1]), 0.0f);
        h[q * 4 + 2] = fmaxf(fmaf(di, v.z, cb2[q * 4 + 2]), 0.0f);
        h[q * 4 + 3] = fmaxf(fmaf(di, v.w, cb2[q * 4 + 3]), 0.0f);
    }

    float l0 = cbfc[0], l1 = cbfc[1];
#pragma unroll
    for (int o = 0; o < H2; o++) {
        l0 = fmaf(h[o], cWfc[o * 2 + 0], l0);
        l1 = fmaf(h[o], cWfc[o * 2 + 1], l1);
    }
    float m = fmaxf(l0, l1);
    float lse = m + logf(expf(l0 - m) + expf(l1 - m));
    float2 r;
    r.x = l0 - lse;
    r.y = l1 - lse;
    ((float2*)out)[i] = r;
}

// ---------------- launch -----------------------------------------------------
extern "C" void kernel_launch(void* const* d_in, const int* in_sizes, int n_in,
                              void* d_out, int out_size) {
    const float* x = (const float*)d_in[0];
    const void*  ei = d_in[1];

    cudaMemcpyToSymbolAsync(cW1,  d_in[2], IN_DIM * H1 * sizeof(float), 0, cudaMemcpyDeviceToDevice);
    cudaMemcpyToSymbolAsync(cb1,  d_in[3], H1 * sizeof(float),          0, cudaMemcpyDeviceToDevice);
    cudaMemcpyToSymbolAsync(cW2,  d_in[4], H1 * H2 * sizeof(float),     0, cudaMemcpyDeviceToDevice);
    cudaMemcpyToSymbolAsync(cb2,  d_in[5], H2 * sizeof(float),          0, cudaMemcpyDeviceToDevice);
    cudaMemcpyToSymbolAsync(cWfc, d_in[6], H2 * 2 * sizeof(float),      0, cudaMemcpyDeviceToDevice);
    cudaMemcpyToSymbolAsync(cbfc, d_in[7], 2 * sizeof(float),           0, cudaMemcpyDeviceToDevice);

    const int B = 256;
    const int GN = (N_NODES + B - 1) / B;
    const int GE = (N_EDGES + B - 1) / B;

    k_detect<<<1, 32>>>((const unsigned*)ei);
    k_deg_init<<<GN, B>>>();
    k_deg_count<<<GE, B>>>(ei);
    k_dinv<<<GN, B>>>();
    k_gemm1<<<GN, B>>>(x);

    long long T1 = (long long)N_EDGES * 8;
    k_scatter1<<<(unsigned)((T1 + B - 1) / B), B>>>(ei);
    k_layer2<<<GN, B>>>();

    long long T2 = (long long)N_EDGES * 4;
    k_scatter2<<<(unsigned)((T2 + B - 1) / B), B>>>(ei);
    k_final<<<GN, B>>>((float*)d_out);
}

// round 2
// speedup vs baseline: 1.0466x; 1.0466x over previous
#include <cuda_runtime.h>
#include <math.h>

#define N_NODES 500000
#define N_EDGES 8000000
#define IN_DIM  128
#define H1      32
#define H2      16

#define SCAN_T   1024
#define SCAN_E   8
#define SCAN_BLK (SCAN_T * SCAN_E)                 // 8192
#define SCAN_NB  ((N_NODES + SCAN_BLK - 1) / SCAN_BLK)  // 62

// ---------------- constant-memory weights -----------------------------------
__constant__ float cW1[IN_DIM * H1];
__constant__ float cb1[H1];
__constant__ float cW2[H1 * H2];
__constant__ float cb2[H2];
__constant__ float cWfc[H2 * 2];
__constant__ float cbfc[2];

// ---------------- scratch (static device globals) ---------------------------
__device__ int      g_src[N_EDGES];
__device__ int      g_dst[N_EDGES];
__device__ int      g_col[N_EDGES];
__device__ unsigned g_deg[N_NODES];
__device__ unsigned g_rowptr[N_NODES + 1];
__device__ unsigned g_cursor[N_NODES];
__device__ unsigned g_bsum[SCAN_NB];
__device__ unsigned g_boff[SCAN_NB];
__device__ float    g_dinv[N_NODES];
__device__ float    g_y1[(size_t)N_NODES * H1];
__device__ float    g_h1[(size_t)N_NODES * H1];
__device__ float    g_y2[(size_t)N_NODES * H2];
__device__ int      g_is64;

// ---------------- edge dtype detect ------------------------------------------
__global__ void k_detect(const unsigned* __restrict__ ei32) {
    if (blockIdx.x == 0 && threadIdx.x == 0) {
        int is64 = 1;
        for (int e = 0; e < 1024; e++)
            if (ei32[2 * e + 1] != 0u) { is64 = 0; break; }
        g_is64 = is64;
    }
}

__global__ void k_deg_init() {
    int i = blockIdx.x * blockDim.x + threadIdx.x;
    if (i < N_NODES) g_deg[i] = 0u;
}

// convert to int32 + count in-degrees
__global__ void k_convert(const void* __restrict__ ei) {
    int e = blockIdx.x * blockDim.x + threadIdx.x;
    if (e >= N_EDGES) return;
    int s, d;
    if (g_is64) {
        const long long* p = (const long long*)ei;
        s = (int)p[e];
        d = (int)p[(long long)N_EDGES + e];
    } else {
        const int* p = (const int*)ei;
        s = p[e];
        d = p[N_EDGES + e];
    }
    g_src[e] = s;
    g_dst[e] = d;
    atomicAdd(&g_deg[d], 1u);
}

__global__ void k_dinv() {
    int i = blockIdx.x * blockDim.x + threadIdx.x;
    if (i < N_NODES) g_dinv[i] = rsqrtf((float)(g_deg[i] + 1u));  // +1 self-loop
}

// ---------------- exclusive scan of indeg -> rowptr --------------------------
__global__ void k_scan_part() {
    __shared__ unsigned sh[SCAN_T];
    int tid = threadIdx.x;
    int base = blockIdx.x * SCAN_BLK + tid * SCAN_E;
    unsigned v[SCAN_E];
    unsigned s = 0;
#pragma unroll
    for (int j = 0; j < SCAN_E; j++) {
        int idx = base + j;
        v[j] = (idx < N_NODES) ? g_deg[idx] : 0u;
        s += v[j];
    }
    sh[tid] = s;
    __syncthreads();
    for (int off = 1; off < SCAN_T; off <<= 1) {
        unsigned t = (tid >= off) ? sh[tid - off] : 0u;
        __syncthreads();
        sh[tid] += t;
        __syncthreads();
    }
    unsigned run = sh[tid] - s;  // exclusive prefix within block
    if (tid == SCAN_T - 1) g_bsum[blockIdx.x] = sh[tid];
#pragma unroll
    for (int j = 0; j < SCAN_E; j++) {
        int idx = base + j;
        if (idx < N_NODES) g_rowptr[idx] = run;
        run += v[j];
    }
}

__global__ void k_scan_sums() {
    __shared__ unsigned sh[64];
    int tid = threadIdx.x;
    unsigned s = (tid < SCAN_NB) ? g_bsum[tid] : 0u;
    sh[tid] = s;
    __syncthreads();
    for (int off = 1; off < 64; off <<= 1) {
        unsigned t = (tid >= off) ? sh[tid - off] : 0u;
        __syncthreads();
        sh[tid] += t;
        __syncthreads();
    }
    if (tid < SCAN_NB) g_boff[tid] = sh[tid] - s;
    if (tid == 63) g_rowptr[N_NODES] = sh[63];  // total = N_EDGES
}

__global__ void k_scan_add() {
    int i = blockIdx.x * blockDim.x + threadIdx.x;
    if (i < N_NODES) {
        g_rowptr[i] += g_boff[i / SCAN_BLK];
        g_cursor[i] = 0u;
    }
}

// ---------------- CSR fill ---------------------------------------------------
__global__ void k_fill() {
    int e = blockIdx.x * blockDim.x + threadIdx.x;
    if (e >= N_EDGES) return;
    int d = g_dst[e];
    unsigned p = g_rowptr[d] + atomicAdd(&g_cursor[d], 1u);
    g_col[p] = g_src[e];
}

// ---------------- layer 1 GEMM: y1 = (x @ W1) * dinv -------------------------
__global__ void k_gemm1(const float* __restrict__ x) {
    int i = blockIdx.x * blockDim.x + threadIdx.x;
    if (i >= N_NODES) return;

    float acc[H1];
#pragma unroll
    for (int o = 0; o < H1; o++) acc[o] = 0.0f;

    const float4* xr = (const float4*)(x + (size_t)i * IN_DIM);
#pragma unroll 2
    for (int kk = 0; kk < IN_DIM / 4; kk++) {
        float4 v = __ldg(xr + kk);
        int k = kk * 4;
#pragma unroll
        for (int o = 0; o < H1; o++) {
            float a = acc[o];
            a = fmaf(v.x, cW1[(k + 0) * H1 + o], a);
            a = fmaf(v.y, cW1[(k + 1) * H1 + o], a);
            a = fmaf(v.z, cW1[(k + 2) * H1 + o], a);
            a = fmaf(v.w, cW1[(k + 3) * H1 + o], a);
            acc[o] = a;
        }
    }

    float di = g_dinv[i];
    float4* y = (float4*)(g_y1 + (size_t)i * H1);
#pragma unroll
    for (int q = 0; q < H1 / 4; q++) {
        float4 t;
        t.x = acc[q * 4 + 0] * di;
        t.y = acc[q * 4 + 1] * di;
        t.z = acc[q * 4 + 2] * di;
        t.w = acc[q * 4 + 3] * di;
        y[q] = t;
    }
}

// ---------------- gather L1 (warp/node) + relu + bias -> h1 ------------------
__global__ void k_gather1() {
    int wid = (blockIdx.x * blockDim.x + threadIdx.x) >> 5;
    int lane = threadIdx.x & 31;
    if (wid >= N_NODES) return;
    int i = wid;

    unsigned beg = g_rowptr[i], end = g_rowptr[i + 1];
    float acc = g_y1[(size_t)i * H1 + lane];  // self-loop term (pre-scaled)

    unsigned j = beg;
    for (; j + 1 < end; j += 2) {
        int s0 = g_col[j];
        int s1 = g_col[j + 1];
        float a = g_y1[(size_t)s0 * H1 + lane];
        float b = g_y1[(size_t)s1 * H1 + lane];
        acc += a;
        acc += b;
    }
    if (j < end) acc += g_y1[(size_t)g_col[j] * H1 + lane];

    float di = g_dinv[i];
    g_h1[(size_t)i * H1 + lane] = fmaxf(fmaf(di, acc, cb1[lane]), 0.0f);
}

// ---------------- layer 2 GEMM: y2 = (h1 @ W2) * dinv ------------------------
__global__ void k_layer2() {
    int i = blockIdx.x * blockDim.x + threadIdx.x;
    if (i >= N_NODES) return;

    float h[H1];
    const float4* hp = (const float4*)(g_h1 + (size_t)i * H1);
#pragma unroll
    for (int q = 0; q < H1 / 4; q++) {
        float4 v = hp[q];
        h[q * 4 + 0] = v.x;
        h[q * 4 + 1] = v.y;
        h[q * 4 + 2] = v.z;
        h[q * 4 + 3] = v.w;
    }

    float acc[H2];
#pragma unroll
    for (int o = 0; o < H2; o++) acc[o] = 0.0f;
#pragma unroll 4
    for (int k = 0; k < H1; k++) {
        float hv = h[k];
#pragma unroll
        for (int o = 0; o < H2; o++)
            acc[o] = fmaf(hv, cW2[k * H2 + o], acc[o]);
    }

    float di = g_dinv[i];
    float4* y = (float4*)(g_y2 + (size_t)i * H2);
#pragma unroll
    for (int q = 0; q < H2 / 4; q++) {
        float4 t;
        t.x = acc[q * 4 + 0] * di;
        t.y = acc[q * 4 + 1] * di;
        t.z = acc[q * 4 + 2] * di;
        t.w = acc[q * 4 + 3] * di;
        y[q] = t;
    }
}

// -------- gather L2 (half-warp/node) + relu + fc + log_softmax -> out --------
__global__ void k_gather2_final(float* __restrict__ out) {
    int tid = blockIdx.x * blockDim.x + threadIdx.x;
    int hwid = tid >> 4;          // half-warp id = node id
    int o = threadIdx.x & 15;     // feature lane
    if (hwid >= N_NODES) return;
    int i = hwid;

    unsigned beg = g_rowptr[i], end = g_rowptr[i + 1];
    float acc = g_y2[(size_t)i * H2 + o];  // self-loop term

    unsigned j = beg;
    for (; j + 1 < end; j += 2) {
        int s0 = g_col[j];
        int s1 = g_col[j + 1];
        float a = g_y2[(size_t)s0 * H2 + o];
        float b = g_y2[(size_t)s1 * H2 + o];
        acc += a;
        acc += b;
    }
    if (j < end) acc += g_y2[(size_t)g_col[j] * H2 + o];

    float di = g_dinv[i];
    float h = fmaxf(fmaf(di, acc, cb2[o]), 0.0f);

    float p0 = h * cWfc[o * 2 + 0];
    float p1 = h * cWfc[o * 2 + 1];
#pragma unroll
    for (int off = 8; off >= 1; off >>= 1) {
        p0 += __shfl_xor_sync(0xffffffffu, p0, off, 16);
        p1 += __shfl_xor_sync(0xffffffffu, p1, off, 16);
    }
    if (o == 0) {
        float l0 = p0 + cbfc[0];
        float l1 = p1 + cbfc[1];
        float m = fmaxf(l0, l1);
        float lse = m + logf(expf(l0 - m) + expf(l1 - m));
        float2 r;
        r.x = l0 - lse;
        r.y = l1 - lse;
        ((float2*)out)[i] = r;
    }
}

// ---------------- launch -----------------------------------------------------
extern "C" void kernel_launch(void* const* d_in, const int* in_sizes, int n_in,
                              void* d_out, int out_size) {
    const float* x = (const float*)d_in[0];
    const void*  ei = d_in[1];

    cudaMemcpyToSymbolAsync(cW1,  d_in[2], IN_DIM * H1 * sizeof(float), 0, cudaMemcpyDeviceToDevice);
    cudaMemcpyToSymbolAsync(cb1,  d_in[3], H1 * sizeof(float),          0, cudaMemcpyDeviceToDevice);
    cudaMemcpyToSymbolAsync(cW2,  d_in[4], H1 * H2 * sizeof(float),     0, cudaMemcpyDeviceToDevice);
    cudaMemcpyToSymbolAsync(cb2,  d_in[5], H2 * sizeof(float),          0, cudaMemcpyDeviceToDevice);
    cudaMemcpyToSymbolAsync(cWfc, d_in[6], H2 * 2 * sizeof(float),      0, cudaMemcpyDeviceToDevice);
    cudaMemcpyToSymbolAsync(cbfc, d_in[7], 2 * sizeof(float),           0, cudaMemcpyDeviceToDevice);

    const int B = 256;
    const int GN = (N_NODES + B - 1) / B;
    const int GE = (N_EDGES + B - 1) / B;

    k_detect<<<1, 32>>>((const unsigned*)ei);
    k_deg_init<<<GN, B>>>();
    k_convert<<<GE, B>>>(ei);
    k_dinv<<<GN, B>>>();

    k_scan_part<<<SCAN_NB, SCAN_T>>>();
    k_scan_sums<<<1, 64>>>();
    k_scan_add<<<GN, B>>>();
    k_fill<<<GE, B>>>();

    k_gemm1<<<GN, B>>>(x);

    // warp per node: 8 nodes per 256-thread block
    k_gather1<<<(N_NODES + 7) / 8, B>>>();
    k_layer2<<<GN, B>>>();
    // half-warp per node: 16 nodes per 256-thread block
    k_gather2_final<<<(N_NODES + 15) / 16, B>>>((float*)d_out);
}